// round 4
// baseline (speedup 1.0000x reference)
#include <cuda_runtime.h>

#define NXg 4096
#define NYg 4096
#define JV  (NYg / 4)   // 1024 float4 lanes per row
#define RSTRIP 16       // rows swept per thread

__global__ __launch_bounds__(256)
void diffreact_sweep(const float* __restrict__ state,
                     const float* __restrict__ bc,
                     const float* __restrict__ a_p,
                     const float* __restrict__ b_p,
                     const float* __restrict__ k_p,
                     float* __restrict__ out)
{
    const int tid   = blockIdx.x * 256 + threadIdx.x;
    const int strip = tid >> 10;          // JV = 1024 = 2^10
    const int jv    = tid & (JV - 1);
    const int lane  = threadIdx.x & 31;   // warps are row-aligned (1024 % 32 == 0)
    const int i0    = strip * RSTRIP;

    const long plane = (long)NXg * NYg;
    const float* __restrict__ U = state;
    const float* __restrict__ V = state + plane;
    float* __restrict__ outU = out;
    float* __restrict__ outV = out + plane;

    // params: a,b,k = sigmoid(x)*0.01 ; fold inv_dx2 = 100 into diffusion coeff
    const float a  = 0.01f / (1.0f + __expf(-__ldg(a_p)));
    const float b  = 0.01f / (1.0f + __expf(-__ldg(b_p)));
    const float k  = 0.01f / (1.0f + __expf(-__ldg(k_p)));
    const float ai = a * 100.0f;
    const float bi = b * 100.0f;

    // bc: [0,0,:]=U {l,r,t,b}; [0,1,:]=V {l,r,t,b}
    const float blU = __ldg(bc + 0), brU = __ldg(bc + 1), btU = __ldg(bc + 2), bbU = __ldg(bc + 3);
    const float blV = __ldg(bc + 4), brV = __ldg(bc + 5), btV = __ldg(bc + 6), bbV = __ldg(bc + 7);

    long base = (long)i0 * NYg + ((long)jv << 2);

    // prime the 3-row window: up (row i0-1), cur (row i0), dn (row i0+1).
    // i0+1 <= NXg-RSTRIP+1 < NXg always, so dn prime needs no bounds check.
    float4 up_u, up_v;
    if (i0 > 0) {
        up_u = *reinterpret_cast<const float4*>(U + base - NYg);
        up_v = *reinterpret_cast<const float4*>(V + base - NYg);
    } else {
        up_u = make_float4(btU, btU, btU, btU);
        up_v = make_float4(btV, btV, btV, btV);
    }
    float4 cu   = *reinterpret_cast<const float4*>(U + base);
    float4 cv   = *reinterpret_cast<const float4*>(V + base);
    float4 dn_u = *reinterpret_cast<const float4*>(U + base + NYg);
    float4 dn_v = *reinterpret_cast<const float4*>(V + base + NYg);

    float4 pf_u, pf_v;   // prefetch buffer (next iteration's down-row)

#pragma unroll
    for (int r = 0; r < RSTRIP; ++r) {
        const int i = i0 + r;

        // Issue the prefetch for the NEXT iteration's down-row (row i+2)
        // before touching this iteration's data: keeps 2 vec-load pairs in
        // flight per warp. Rows i0+2 .. i0+RSTRIP are the only ones used.
        if (r + 2 <= RSTRIP) {
            if (i + 2 < NXg) {
                pf_u = *reinterpret_cast<const float4*>(U + base + 2 * NYg);
                pf_v = *reinterpret_cast<const float4*>(V + base + 2 * NYg);
            } else {  // dn for the last physical row -> bottom bc
                pf_u = make_float4(bbU, bbU, bbU, bbU);
                pf_v = make_float4(bbV, bbV, bbV, bbV);
            }
        }

        // horizontal halos via warp shuffle; lanes 0/31 patch from gmem / bc
        float ul = __shfl_up_sync(0xffffffffu, cu.w, 1);
        float vl = __shfl_up_sync(0xffffffffu, cv.w, 1);
        float ur = __shfl_down_sync(0xffffffffu, cu.x, 1);
        float vr = __shfl_down_sync(0xffffffffu, cv.x, 1);
        if (lane == 0) {
            ul = (jv > 0) ? __ldg(U + base - 1) : blU;
            vl = (jv > 0) ? __ldg(V + base - 1) : blV;
        }
        if (lane == 31) {
            ur = (jv < JV - 1) ? __ldg(U + base + 4) : brU;
            vr = (jv < JV - 1) ? __ldg(V + base + 4) : brV;
        }

        // 5-point laplacian sums (inv_dx2 folded into ai/bi)
        float4 lu, lv;
        lu.x = up_u.x + dn_u.x + ul   + cu.y - 4.0f * cu.x;
        lu.y = up_u.y + dn_u.y + cu.x + cu.z - 4.0f * cu.y;
        lu.z = up_u.z + dn_u.z + cu.y + cu.w - 4.0f * cu.z;
        lu.w = up_u.w + dn_u.w + cu.z + ur   - 4.0f * cu.w;

        lv.x = up_v.x + dn_v.x + vl   + cv.y - 4.0f * cv.x;
        lv.y = up_v.y + dn_v.y + cv.x + cv.z - 4.0f * cv.y;
        lv.z = up_v.z + dn_v.z + cv.y + cv.w - 4.0f * cv.z;
        lv.w = up_v.w + dn_v.w + cv.z + vr   - 4.0f * cv.w;

        // dU = a*lapU + U - U^3 - V - k ; dV = b*lapV + U - V
        float4 dU, dV;
        dU.x = fmaf(ai, lu.x, cu.x - cu.x * cu.x * cu.x - cv.x - k);
        dU.y = fmaf(ai, lu.y, cu.y - cu.y * cu.y * cu.y - cv.y - k);
        dU.z = fmaf(ai, lu.z, cu.z - cu.z * cu.z * cu.z - cv.z - k);
        dU.w = fmaf(ai, lu.w, cu.w - cu.w * cu.w * cu.w - cv.w - k);

        dV.x = fmaf(bi, lv.x, cu.x - cv.x);
        dV.y = fmaf(bi, lv.y, cu.y - cv.y);
        dV.z = fmaf(bi, lv.z, cu.z - cv.z);
        dV.w = fmaf(bi, lv.w, cu.w - cv.w);

        *reinterpret_cast<float4*>(outU + base) = dU;
        *reinterpret_cast<float4*>(outV + base) = dV;

        // rotate the row window
        up_u = cu;   up_v = cv;
        cu   = dn_u; cv   = dn_v;
        dn_u = pf_u; dn_v = pf_v;
        base += NYg;
    }
}

extern "C" void kernel_launch(void* const* d_in, const int* in_sizes, int n_in,
                              void* d_out, int out_size)
{
    const float* state = (const float*)d_in[0];  // (1,2,4096,4096) f32
    const float* bc    = (const float*)d_in[1];  // (1,2,4) f32
    const float* a_p   = (const float*)d_in[2];
    const float* b_p   = (const float*)d_in[3];
    const float* k_p   = (const float*)d_in[4];
    float* out = (float*)d_out;

    const int total_threads = (NXg / RSTRIP) * JV;  // 256 * 1024 = 262144
    const int threads = 256;
    const int blocks  = total_threads / threads;    // 1024
    diffreact_sweep<<<blocks, threads>>>(state, bc, a_p, b_p, k_p, out);
}

// round 5
// speedup vs baseline: 1.0856x; 1.0856x over previous
#include <cuda_runtime.h>

#define NXg 4096
#define NYg 4096
#define JV  (NYg / 4)   // 1024 float4 lanes per row
#define RSTRIP 8        // rows swept per thread

__global__ __launch_bounds__(256, 5)
void diffreact_sweep(const float* __restrict__ state,
                     const float* __restrict__ bc,
                     const float* __restrict__ a_p,
                     const float* __restrict__ b_p,
                     const float* __restrict__ k_p,
                     float* __restrict__ out)
{
    const int tid   = blockIdx.x * 256 + threadIdx.x;
    const int strip = tid >> 10;          // JV = 1024 = 2^10
    const int jv    = tid & (JV - 1);
    const int lane  = threadIdx.x & 31;   // warps are row-aligned (1024 % 32 == 0)
    const int i0    = strip * RSTRIP;

    const long plane = (long)NXg * NYg;
    const float* __restrict__ U = state;
    const float* __restrict__ V = state + plane;
    float* __restrict__ outU = out;
    float* __restrict__ outV = out + plane;

    // params: a,b,k = sigmoid(x)*0.01 ; fold inv_dx2 = 100 into diffusion coeff
    const float a  = 0.01f / (1.0f + __expf(-__ldg(a_p)));
    const float b  = 0.01f / (1.0f + __expf(-__ldg(b_p)));
    const float k  = 0.01f / (1.0f + __expf(-__ldg(k_p)));
    const float ai = a * 100.0f;
    const float bi = b * 100.0f;

    // bc: [0,0,:]=U {l,r,t,b}; [0,1,:]=V {l,r,t,b}
    const float blU = __ldg(bc + 0), brU = __ldg(bc + 1), btU = __ldg(bc + 2), bbU = __ldg(bc + 3);
    const float blV = __ldg(bc + 4), brV = __ldg(bc + 5), btV = __ldg(bc + 6), bbV = __ldg(bc + 7);

    long base = (long)i0 * NYg + ((long)jv << 2);

    // prime: up-row and current row
    float4 up_u, up_v;
    if (i0 > 0) {
        up_u = *reinterpret_cast<const float4*>(U + base - NYg);
        up_v = *reinterpret_cast<const float4*>(V + base - NYg);
    } else {
        up_u = make_float4(btU, btU, btU, btU);
        up_v = make_float4(btV, btV, btV, btV);
    }
    float4 cu = *reinterpret_cast<const float4*>(U + base);
    float4 cv = *reinterpret_cast<const float4*>(V + base);

#pragma unroll
    for (int r = 0; r < RSTRIP; ++r) {
        const int i = i0 + r;

        // next (down) row
        float4 dn_u, dn_v;
        if (i < NXg - 1) {
            dn_u = *reinterpret_cast<const float4*>(U + base + NYg);
            dn_v = *reinterpret_cast<const float4*>(V + base + NYg);
        } else {
            dn_u = make_float4(bbU, bbU, bbU, bbU);
            dn_v = make_float4(bbV, bbV, bbV, bbV);
        }

        // horizontal halos via warp shuffle; lanes 0/31 patch from gmem / bc
        float ul = __shfl_up_sync(0xffffffffu, cu.w, 1);
        float vl = __shfl_up_sync(0xffffffffu, cv.w, 1);
        float ur = __shfl_down_sync(0xffffffffu, cu.x, 1);
        float vr = __shfl_down_sync(0xffffffffu, cv.x, 1);
        if (lane == 0) {
            ul = (jv > 0) ? __ldg(U + base - 1) : blU;
            vl = (jv > 0) ? __ldg(V + base - 1) : blV;
        }
        if (lane == 31) {
            ur = (jv < JV - 1) ? __ldg(U + base + 4) : brU;
            vr = (jv < JV - 1) ? __ldg(V + base + 4) : brV;
        }

        // 5-point laplacian sums (inv_dx2 folded into ai/bi)
        float4 lu, lv;
        lu.x = up_u.x + dn_u.x + ul   + cu.y - 4.0f * cu.x;
        lu.y = up_u.y + dn_u.y + cu.x + cu.z - 4.0f * cu.y;
        lu.z = up_u.z + dn_u.z + cu.y + cu.w - 4.0f * cu.z;
        lu.w = up_u.w + dn_u.w + cu.z + ur   - 4.0f * cu.w;

        lv.x = up_v.x + dn_v.x + vl   + cv.y - 4.0f * cv.x;
        lv.y = up_v.y + dn_v.y + cv.x + cv.z - 4.0f * cv.y;
        lv.z = up_v.z + dn_v.z + cv.y + cv.w - 4.0f * cv.z;
        lv.w = up_v.w + dn_v.w + cv.z + vr   - 4.0f * cv.w;

        // dU = a*lapU + U - U^3 - V - k ; dV = b*lapV + U - V
        float4 dU, dV;
        dU.x = fmaf(ai, lu.x, cu.x - cu.x * cu.x * cu.x - cv.x - k);
        dU.y = fmaf(ai, lu.y, cu.y - cu.y * cu.y * cu.y - cv.y - k);
        dU.z = fmaf(ai, lu.z, cu.z - cu.z * cu.z * cu.z - cv.z - k);
        dU.w = fmaf(ai, lu.w, cu.w - cu.w * cu.w * cu.w - cv.w - k);

        dV.x = fmaf(bi, lv.x, cu.x - cv.x);
        dV.y = fmaf(bi, lv.y, cu.y - cv.y);
        dV.z = fmaf(bi, lv.z, cu.z - cv.z);
        dV.w = fmaf(bi, lv.w, cu.w - cv.w);

        // streaming stores: output is never re-read; keep L2 for input reuse
        __stcs(reinterpret_cast<float4*>(outU + base), dU);
        __stcs(reinterpret_cast<float4*>(outV + base), dV);

        // rotate the row window
        up_u = cu; up_v = cv;
        cu = dn_u; cv = dn_v;
        base += NYg;
    }
}

extern "C" void kernel_launch(void* const* d_in, const int* in_sizes, int n_in,
                              void* d_out, int out_size)
{
    const float* state = (const float*)d_in[0];  // (1,2,4096,4096) f32
    const float* bc    = (const float*)d_in[1];  // (1,2,4) f32
    const float* a_p   = (const float*)d_in[2];
    const float* b_p   = (const float*)d_in[3];
    const float* k_p   = (const float*)d_in[4];
    float* out = (float*)d_out;

    const int total_threads = (NXg / RSTRIP) * JV;  // 512 * 1024 = 524288
    const int threads = 256;
    const int blocks  = total_threads / threads;    // 2048
    diffreact_sweep<<<blocks, threads>>>(state, bc, a_p, b_p, k_p, out);
}